// round 11
// baseline (speedup 1.0000x reference)
#include <cuda_runtime.h>
#include <cuda_bf16.h>
#include <math.h>
#include <stdint.h>

#define BATCH 512
#define SEQT  200
#define HID   128
#define GATES 512   // 4H
#define EMB   128
#define MTOT  (BATCH*SEQT)   // 102400

// ---------------- static scratch ----------------
__device__ float g_zx_fw[(size_t)MTOT * GATES];
__device__ float g_zx_bw[(size_t)MTOT * GATES];
__device__ float g_s0f[(size_t)MTOT * HID];
__device__ float g_s0b[(size_t)MTOT * HID];
__device__ float g_s1f[(size_t)MTOT * HID];
__device__ float g_s1b[(size_t)MTOT * HID];
__device__ uint32_t g_Wtb[4 * GATES * (EMB/2)];      // bf16x2 W^T: [4][n=512][k2=64]
__device__ uint32_t g_UfragB[4 * 64 * 4 * 32 * 4];   // bf16 U fragments (m16n8k16)

// ---------------- helpers ----------------
__device__ __forceinline__ float rcp_(float x) {
    float y; asm("rcp.approx.f32 %0, %1;" : "=f"(y) : "f"(x)); return y;
}
__device__ __forceinline__ float ex2_(float x) {
    float y; asm("ex2.approx.f32 %0, %1;" : "=f"(y) : "f"(x)); return y;
}
__device__ __forceinline__ float sigm(float x) {
    return rcp_(1.f + ex2_(-1.4426950408889634f * x));
}
__device__ __forceinline__ float tanh_(float x) {
    return 1.f - 2.f * rcp_(1.f + ex2_(2.8853900817779268f * x));
}
__device__ __forceinline__ uint32_t bf2(float lo, float hi) {
    __nv_bfloat162 v = __floats2bfloat162_rn(lo, hi);
    return *(uint32_t*)&v;
}

__device__ __forceinline__ void mma_bf16(float* d, const uint32_t* a, uint32_t b0, uint32_t b1) {
    asm volatile(
        "mma.sync.aligned.m16n8k16.row.col.f32.bf16.bf16.f32 "
        "{%0,%1,%2,%3}, {%4,%5,%6,%7}, {%8,%9}, {%0,%1,%2,%3};"
        : "+f"(d[0]), "+f"(d[1]), "+f"(d[2]), "+f"(d[3])
        : "r"(a[0]), "r"(a[1]), "r"(a[2]), "r"(a[3]), "r"(b0), "r"(b1));
}

// ---------------- bf16 tensor-core GEMM: C[m,n] = A[m,k] @ Wt[n,k]^T + bias[n] ----------------
// Block tile M=128, N=64, K=128 single pass. 256 thr = 8 warps (2m x 4n);
// warp tile 64x16 -> acc 32 regs; ~90 regs total -> 2 blocks/SM.
#define LDB2 68   // uint32 stride; 68%32==4 -> conflict-free fragment loads
#define GSMEM ((128 + 64) * LDB2 * 4)   // ~52KB

__global__ __launch_bounds__(256, 2) void gemm_bf(
    const float* __restrict__ A, const uint32_t* __restrict__ Wtb,
    const float* __restrict__ bias, float* __restrict__ C)
{
    extern __shared__ __align__(16) char smem[];
    uint32_t (*As2)[LDB2] = (uint32_t(*)[LDB2])smem;                         // [128][68]
    uint32_t (*Bs2)[LDB2] = (uint32_t(*)[LDB2])(smem + 128 * LDB2 * 4);      // [64][68]

    const int tid = threadIdx.x;
    const int wid = tid >> 5;
    const int lane = tid & 31;
    const int wm = wid & 1;        // 0..1  (64 m-rows each)
    const int wn = wid >> 1;       // 0..3  (16 n-cols each)
    const int g = lane >> 2;
    const int tig = lane & 3;

    const size_t m0 = (size_t)blockIdx.y * 128;
    const int n0 = blockIdx.x * 64;

    // stage A: 128 rows x 32 float4 -> bf16x2 pairs
#pragma unroll
    for (int i = 0; i < 16; i++) {
        int idx = tid + i * 256;       // 0..4095
        int row = idx >> 5;
        int c4  = idx & 31;
        float4 va = *(const float4*)&A[(m0 + row) * EMB + c4 * 4];
        uint2 u = { bf2(va.x, va.y), bf2(va.z, va.w) };
        *(uint2*)&As2[row][c4 * 2] = u;
    }
    // stage B: 64 rows x 16 uint4
#pragma unroll
    for (int i = 0; i < 4; i++) {
        int idx = tid + i * 256;       // 0..1023
        int row = idx >> 4;            // 0..63
        int c4  = idx & 15;
        uint4 v = *(const uint4*)&Wtb[(size_t)(n0 + row) * (EMB/2) + c4 * 4];
        *(uint4*)&Bs2[row][c4 * 4] = v;
    }
    __syncthreads();

    float acc[4][2][4];
#pragma unroll
    for (int mt = 0; mt < 4; mt++)
#pragma unroll
        for (int nt = 0; nt < 2; nt++)
#pragma unroll
            for (int q = 0; q < 4; q++) acc[mt][nt][q] = 0.f;

#pragma unroll
    for (int k8 = 0; k8 < 8; k8++) {
        const int kh = k8 * 8;
        uint32_t af[4][4];
#pragma unroll
        for (int mt = 0; mt < 4; mt++) {
            int r = wm * 64 + mt * 16 + g;
            af[mt][0] = As2[r][kh + tig];
            af[mt][1] = As2[r + 8][kh + tig];
            af[mt][2] = As2[r][kh + 4 + tig];
            af[mt][3] = As2[r + 8][kh + 4 + tig];
        }
#pragma unroll
        for (int nt = 0; nt < 2; nt++) {
            int n = wn * 16 + nt * 8 + g;
            uint32_t b0 = Bs2[n][kh + tig];
            uint32_t b1 = Bs2[n][kh + 4 + tig];
#pragma unroll
            for (int mt = 0; mt < 4; mt++)
                mma_bf16(acc[mt][nt], af[mt], b0, b1);
        }
    }

#pragma unroll
    for (int nt = 0; nt < 2; nt++) {
        int col = n0 + wn * 16 + nt * 8 + 2 * tig;
        float b0 = bias[col], b1 = bias[col + 1];
#pragma unroll
        for (int mt = 0; mt < 4; mt++) {
            size_t row = m0 + wm * 64 + mt * 16 + g;
            float2 o0 = { acc[mt][nt][0] + b0, acc[mt][nt][1] + b1 };
            float2 o1 = { acc[mt][nt][2] + b0, acc[mt][nt][3] + b1 };
            *(float2*)&C[row * GATES + col] = o0;
            *(float2*)&C[(row + 8) * GATES + col] = o1;
        }
    }
}

// ---------------- W -> bf16x2 transposed: Wtb[u][n][k2] ----------------
__global__ void build_wtb(const float* __restrict__ W, uint32_t* __restrict__ Wtb)
{
    int idx = blockIdx.x * blockDim.x + threadIdx.x;   // over 4*512*64
    if (idx < 4 * GATES * (EMB/2)) {
        int k2 = idx & 63;
        int n  = (idx >> 6) & 511;
        int u  = idx >> 15;
        const float* Wb = W + (size_t)u * (EMB * GATES);
        Wtb[idx] = bf2(Wb[(size_t)(2*k2) * GATES + n], Wb[(size_t)(2*k2+1) * GATES + n]);
    }
}

// ---------------- bf16 U fragment pre-swizzle (m16n8k16, kt-pair packed) ----------------
__global__ void build_ufragb(const float* __restrict__ U, uint32_t* __restrict__ UFB)
{
    int idx = blockIdx.x * blockDim.x + threadIdx.x;
    if (idx < 4 * 64 * 4 * 32 * 4) {
        int q    = idx & 3;
        int lane = (idx >> 2) & 31;
        int kt2  = (idx >> 7) & 3;
        int ntg  = (idx >> 9) & 63;
        int u    = idx >> 15;
        int tig = lane & 3, gg = lane >> 2;
        int kt  = kt2 * 2 + (q >> 1);
        int reg = q & 1;
        int k_lo = kt * 16 + reg * 8 + 2 * tig;
        int n = ntg * 8 + gg;
        const float* Ub = U + (size_t)u * (EMB * GATES);
        UFB[idx] = bf2(Ub[(size_t)k_lo * GATES + n], Ub[(size_t)(k_lo + 1) * GATES + n]);
    }
}

// ---------------- fused bf16 tensor-core LSTM recurrence (unchanged) ----------------
__global__ __launch_bounds__(512) void lstm_tc(
    const float* __restrict__ zx_fw, const float* __restrict__ zx_bw,
    const uint32_t* __restrict__ uf_fw, const uint32_t* __restrict__ uf_bw,
    float* __restrict__ out_fw, float* __restrict__ out_bw)
{
    const int dir = blockIdx.y;
    const float* __restrict__ zx = dir ? zx_bw : zx_fw;
    const uint32_t* __restrict__ uf = dir ? uf_bw : uf_fw;
    float* __restrict__ out = dir ? out_bw : out_fw;

    const int b0  = blockIdx.x * 8;
    const int tid = threadIdx.x;
    const int w   = tid >> 5;
    const int lane = tid & 31;
    const int g = lane >> 2;
    const int tig = lane & 3;
    const int col0 = 8 * w + 2 * tig;

    __shared__ __align__(16) uint32_t h2[2][16][68];

    for (int q2 = tid; q2 < 2 * 16 * 68; q2 += 512) ((uint32_t*)h2)[q2] = 0u;
    float c0 = 0.f, c1 = 0.f;

    const uint4* ufp[4];
#pragma unroll
    for (int nt = 0; nt < 4; nt++)
        ufp[nt] = (const uint4*)uf + (size_t)(w + 16 * nt) * 4 * 32 + lane;

    const float* zr0 = zx + ((size_t)(b0 + g) * SEQT) * GATES + col0;
    float* or0 = out + ((size_t)(b0 + g) * SEQT) * HID + col0;

    __syncthreads();

    for (int s = 0; s < SEQT; s++) {
        const int t = dir ? (SEQT - 1 - s) : s;
        const int rb = s & 1;
        const int wb = rb ^ 1;

        float2 zv0[4];
#pragma unroll
        for (int nt = 0; nt < 4; nt++)
            zv0[nt] = *(const float2*)&zr0[(size_t)t * GATES + 128 * nt];

        float acc[4][4];
#pragma unroll
        for (int nt = 0; nt < 4; nt++)
#pragma unroll
            for (int q = 0; q < 4; q++) acc[nt][q] = 0.f;

        uint4 bv[4];
#pragma unroll
        for (int nt = 0; nt < 4; nt++) bv[nt] = ufp[nt][0];

#pragma unroll
        for (int kt2 = 0; kt2 < 4; kt2++) {
            uint4 nb[4];
            if (kt2 < 3) {
#pragma unroll
                for (int nt = 0; nt < 4; nt++) nb[nt] = ufp[nt][(kt2 + 1) * 32];
            }
            const int kbe = kt2 * 16;
            uint32_t ae[4], ao[4];
            ae[0] = h2[rb][g][kbe + tig];
            ae[1] = h2[rb][g + 8][kbe + tig];
            ae[2] = h2[rb][g][kbe + tig + 4];
            ae[3] = h2[rb][g + 8][kbe + tig + 4];
            ao[0] = h2[rb][g][kbe + 8 + tig];
            ao[1] = h2[rb][g + 8][kbe + 8 + tig];
            ao[2] = h2[rb][g][kbe + 8 + tig + 4];
            ao[3] = h2[rb][g + 8][kbe + 8 + tig + 4];
#pragma unroll
            for (int nt = 0; nt < 4; nt++) {
                mma_bf16(acc[nt], ae, bv[nt].x, bv[nt].y);
                mma_bf16(acc[nt], ao, bv[nt].z, bv[nt].w);
            }
#pragma unroll
            for (int nt = 0; nt < 4; nt++) bv[nt] = nb[nt];
        }

        float h00, h01;
        {
            float ig = sigm(acc[0][0] + zv0[0].x), fg = sigm(acc[1][0] + zv0[1].x);
            float gg = tanh_(acc[2][0] + zv0[2].x), og = sigm(acc[3][0] + zv0[3].x);
            c0 = fg * c0 + ig * gg;  h00 = og * tanh_(c0);
        }
        {
            float ig = sigm(acc[0][1] + zv0[0].y), fg = sigm(acc[1][1] + zv0[1].y);
            float gg = tanh_(acc[2][1] + zv0[2].y), og = sigm(acc[3][1] + zv0[3].y);
            c1 = fg * c1 + ig * gg;  h01 = og * tanh_(c1);
        }

        h2[wb][g][col0 >> 1] = bf2(h00, h01);
        *(float2*)&or0[(size_t)t * HID] = make_float2(h00, h01);

        __syncthreads();
    }
}

// ---------------- final combine ----------------
__global__ void combine(const float* __restrict__ a, const float* __restrict__ b,
                        const float* __restrict__ c, const float* __restrict__ d,
                        float* __restrict__ out, int n4)
{
    int i = blockIdx.x * blockDim.x + threadIdx.x;
    if (i < n4) {
        float4 va = ((const float4*)a)[i];
        float4 vb = ((const float4*)b)[i];
        float4 vc = ((const float4*)c)[i];
        float4 vd = ((const float4*)d)[i];
        float4 o;
        o.x = 0.5f * (va.x + vb.x + vc.x + vd.x);
        o.y = 0.5f * (va.y + vb.y + vc.y + vd.y);
        o.z = 0.5f * (va.z + vb.z + vc.z + vd.z);
        o.w = 0.5f * (va.w + vb.w + vc.w + vd.w);
        ((float4*)out)[i] = o;
    }
}

// ---------------- launch ----------------
extern "C" void kernel_launch(void* const* d_in, const int* in_sizes, int n_in,
                              void* d_out, int out_size)
{
    const float* x = (const float*)d_in[0];
    const float* W = (const float*)d_in[1];
    const float* U = (const float*)d_in[2];
    const float* b = (const float*)d_in[3];

    float *zxf, *zxb, *s0f, *s0b, *s1f, *s1b;
    uint32_t *Wtb, *UFB;
    cudaGetSymbolAddress((void**)&zxf, g_zx_fw);
    cudaGetSymbolAddress((void**)&zxb, g_zx_bw);
    cudaGetSymbolAddress((void**)&s0f, g_s0f);
    cudaGetSymbolAddress((void**)&s0b, g_s0b);
    cudaGetSymbolAddress((void**)&s1f, g_s1f);
    cudaGetSymbolAddress((void**)&s1b, g_s1b);
    cudaGetSymbolAddress((void**)&Wtb, g_Wtb);
    cudaGetSymbolAddress((void**)&UFB, g_UfragB);

    cudaFuncSetAttribute(gemm_bf, cudaFuncAttributeMaxDynamicSharedMemorySize, GSMEM);

    const size_t WBSZ = (size_t)GATES * (EMB/2);   // 32768 uint32
    const size_t UFSZ = 64 * 4 * 32 * 4;           // 32768 uint32
    const float* b00 = b;           const float* b01 = b + GATES;
    const float* b10 = b + 2*GATES; const float* b11 = b + 3*GATES;
    uint32_t* Wt00 = Wtb;            uint32_t* Wt01 = Wtb + WBSZ;
    uint32_t* Wt10 = Wtb + 2*WBSZ;   uint32_t* Wt11 = Wtb + 3*WBSZ;
    uint32_t* UF00 = UFB;            uint32_t* UF01 = UFB + UFSZ;
    uint32_t* UF10 = UFB + 2*UFSZ;   uint32_t* UF11 = UFB + 3*UFSZ;

    build_wtb<<<(4 * GATES * (EMB/2) + 255) / 256, 256>>>(W, Wtb);
    build_ufragb<<<(4 * 64 * 4 * 32 * 4 + 255) / 256, 256>>>(U, UFB);

    dim3 gg(GATES / 64, MTOT / 128);    // (8, 800) = 6400 blocks
    dim3 lg(BATCH / 8, 2);              // (64, 2)

    gemm_bf<<<gg, 256, GSMEM>>>(x, Wt00, b00, zxf);
    gemm_bf<<<gg, 256, GSMEM>>>(x, Wt01, b01, zxb);
    lstm_tc<<<lg, 512>>>(zxf, zxb, UF00, UF01, s0f, s0b);

    gemm_bf<<<gg, 256, GSMEM>>>(s0f, Wt10, b10, zxf);
    gemm_bf<<<gg, 256, GSMEM>>>(s0b, Wt11, b11, zxb);
    lstm_tc<<<lg, 512>>>(zxf, zxb, UF10, UF11, s1f, s1b);

    int n4 = MTOT * HID / 4;
    combine<<<(n4 + 255) / 256, 256>>>(s1f, s0f, s1b, s0b, (float*)d_out, n4);
}

// round 12
// speedup vs baseline: 1.0853x; 1.0853x over previous
#include <cuda_runtime.h>
#include <cuda_bf16.h>
#include <cuda_fp16.h>
#include <math.h>
#include <stdint.h>

#define BATCH 512
#define SEQT  200
#define HID   128
#define GATES 512   // 4H
#define EMB   128
#define MTOT  (BATCH*SEQT)   // 102400

// ---------------- static scratch ----------------
__device__ __half g_zx_fw[(size_t)MTOT * GATES];     // fp16 zx, 105MB
__device__ __half g_zx_bw[(size_t)MTOT * GATES];
__device__ float g_s0f[(size_t)MTOT * HID];
__device__ float g_s0b[(size_t)MTOT * HID];
__device__ float g_s1f[(size_t)MTOT * HID];
__device__ float g_s1b[(size_t)MTOT * HID];
__device__ uint32_t g_xb[(size_t)MTOT * EMB / 2];    // bf16x2 x
__device__ uint32_t g_hb0f[(size_t)MTOT * HID / 2];  // bf16x2 layer-0 h (fw)
__device__ uint32_t g_hb0b[(size_t)MTOT * HID / 2];  // bf16x2 layer-0 h (bw)
__device__ uint32_t g_Wtb[4 * GATES * (EMB/2)];      // bf16x2 W^T: [4][n=512][k2=64]
__device__ uint32_t g_UfragB[4 * 64 * 4 * 32 * 4];   // bf16 U fragments (m16n8k16)

// ---------------- helpers ----------------
__device__ __forceinline__ float rcp_(float x) {
    float y; asm("rcp.approx.f32 %0, %1;" : "=f"(y) : "f"(x)); return y;
}
__device__ __forceinline__ float ex2_(float x) {
    float y; asm("ex2.approx.f32 %0, %1;" : "=f"(y) : "f"(x)); return y;
}
__device__ __forceinline__ float sigm(float x) {
    return rcp_(1.f + ex2_(-1.4426950408889634f * x));
}
__device__ __forceinline__ float tanh_(float x) {
    return 1.f - 2.f * rcp_(1.f + ex2_(2.8853900817779268f * x));
}
__device__ __forceinline__ uint32_t bf2(float lo, float hi) {
    __nv_bfloat162 v = __floats2bfloat162_rn(lo, hi);
    return *(uint32_t*)&v;
}
__device__ __forceinline__ uint32_t smem_u32(const void* p) {
    uint32_t a;
    asm("{ .reg .u64 t; cvta.to.shared.u64 t, %1; cvt.u32.u64 %0, t; }" : "=r"(a) : "l"(p));
    return a;
}
__device__ __forceinline__ void cp16(uint32_t s, const void* g) {
    asm volatile("cp.async.cg.shared.global [%0], [%1], 16;" :: "r"(s), "l"(g));
}

__device__ __forceinline__ void mma_bf16(float* d, const uint32_t* a, uint32_t b0, uint32_t b1) {
    asm volatile(
        "mma.sync.aligned.m16n8k16.row.col.f32.bf16.bf16.f32 "
        "{%0,%1,%2,%3}, {%4,%5,%6,%7}, {%8,%9}, {%0,%1,%2,%3};"
        : "+f"(d[0]), "+f"(d[1]), "+f"(d[2]), "+f"(d[3])
        : "r"(a[0]), "r"(a[1]), "r"(a[2]), "r"(a[3]), "r"(b0), "r"(b1));
}

// ---------------- bf16 GEMM: C[m,n] = A[m,k] @ Wt[n,k]^T + bias[n], C fp16 ----------------
// A pre-converted bf16x2 [MTOT][64]. Tile M=128,N=128,K=128 single pass, cp.async staging.
// 256 thr = 8 warps (2m x 4n); warp tile 64x32.
#define LDB2 68
#define GSMEM (2 * 128 * LDB2 * 4)   // ~68KB

__global__ __launch_bounds__(256, 2) void gemm_bf(
    const uint32_t* __restrict__ A2, const uint32_t* __restrict__ Wtb,
    const float* __restrict__ bias, __half* __restrict__ C)
{
    extern __shared__ __align__(16) char smem[];
    uint32_t (*As2)[LDB2] = (uint32_t(*)[LDB2])smem;                         // [128][68]
    uint32_t (*Bs2)[LDB2] = (uint32_t(*)[LDB2])(smem + 128 * LDB2 * 4);      // [128][68]

    const int tid = threadIdx.x;
    const int wid = tid >> 5;
    const int lane = tid & 31;
    const int wm = wid & 1;
    const int wn = wid >> 1;
    const int g = lane >> 2;
    const int tig = lane & 3;

    const size_t m0 = (size_t)blockIdx.y * 128;
    const int n0 = blockIdx.x * 128;

    // stage A and B via cp.async: 16 uint4 chunks per row, 8 chunks per thread each
#pragma unroll
    for (int i = 0; i < 8; i++) {
        int idx = tid + i * 256;       // 0..2047
        int row = idx >> 4;
        int c4  = idx & 15;
        cp16(smem_u32(&As2[row][c4 * 4]), A2 + (m0 + row) * (EMB/2) + c4 * 4);
        cp16(smem_u32(&Bs2[row][c4 * 4]), Wtb + (size_t)(n0 + row) * (EMB/2) + c4 * 4);
    }
    asm volatile("cp.async.commit_group;");
    asm volatile("cp.async.wait_group 0;" ::: "memory");
    __syncthreads();

    float acc[4][4][4];
#pragma unroll
    for (int mt = 0; mt < 4; mt++)
#pragma unroll
        for (int nt = 0; nt < 4; nt++)
#pragma unroll
            for (int q = 0; q < 4; q++) acc[mt][nt][q] = 0.f;

#pragma unroll
    for (int k8 = 0; k8 < 8; k8++) {
        const int kh = k8 * 8;
        uint32_t af[4][4];
#pragma unroll
        for (int mt = 0; mt < 4; mt++) {
            int r = wm * 64 + mt * 16 + g;
            af[mt][0] = As2[r][kh + tig];
            af[mt][1] = As2[r + 8][kh + tig];
            af[mt][2] = As2[r][kh + 4 + tig];
            af[mt][3] = As2[r + 8][kh + 4 + tig];
        }
#pragma unroll
        for (int nt = 0; nt < 4; nt++) {
            int n = wn * 32 + nt * 8 + g;
            uint32_t b0 = Bs2[n][kh + tig];
            uint32_t b1 = Bs2[n][kh + 4 + tig];
#pragma unroll
            for (int mt = 0; mt < 4; mt++)
                mma_bf16(acc[mt][nt], af[mt], b0, b1);
        }
    }

#pragma unroll
    for (int nt = 0; nt < 4; nt++) {
        int col = n0 + wn * 32 + nt * 8 + 2 * tig;
        float b0 = bias[col], b1 = bias[col + 1];
#pragma unroll
        for (int mt = 0; mt < 4; mt++) {
            size_t row = m0 + wm * 64 + mt * 16 + g;
            __half2 o0 = __floats2half2_rn(acc[mt][nt][0] + b0, acc[mt][nt][1] + b1);
            __half2 o1 = __floats2half2_rn(acc[mt][nt][2] + b0, acc[mt][nt][3] + b1);
            *(__half2*)&C[row * GATES + col] = o0;
            *(__half2*)&C[(row + 8) * GATES + col] = o1;
        }
    }
}

// ---------------- x -> bf16x2 ----------------
__global__ void convert_x(const float* __restrict__ x, uint32_t* __restrict__ xb, int n2)
{
    int i = blockIdx.x * blockDim.x + threadIdx.x;
    if (i < n2) {
        float2 v = ((const float2*)x)[i];
        xb[i] = bf2(v.x, v.y);
    }
}

// ---------------- W -> bf16x2 transposed ----------------
__global__ void build_wtb(const float* __restrict__ W, uint32_t* __restrict__ Wtb)
{
    int idx = blockIdx.x * blockDim.x + threadIdx.x;
    if (idx < 4 * GATES * (EMB/2)) {
        int k2 = idx & 63;
        int n  = (idx >> 6) & 511;
        int u  = idx >> 15;
        const float* Wb = W + (size_t)u * (EMB * GATES);
        Wtb[idx] = bf2(Wb[(size_t)(2*k2) * GATES + n], Wb[(size_t)(2*k2+1) * GATES + n]);
    }
}

// ---------------- bf16 U fragment pre-swizzle ----------------
__global__ void build_ufragb(const float* __restrict__ U, uint32_t* __restrict__ UFB)
{
    int idx = blockIdx.x * blockDim.x + threadIdx.x;
    if (idx < 4 * 64 * 4 * 32 * 4) {
        int q    = idx & 3;
        int lane = (idx >> 2) & 31;
        int kt2  = (idx >> 7) & 3;
        int ntg  = (idx >> 9) & 63;
        int u    = idx >> 15;
        int tig = lane & 3, gg = lane >> 2;
        int kt  = kt2 * 2 + (q >> 1);
        int reg = q & 1;
        int k_lo = kt * 16 + reg * 8 + 2 * tig;
        int n = ntg * 8 + gg;
        const float* Ub = U + (size_t)u * (EMB * GATES);
        UFB[idx] = bf2(Ub[(size_t)k_lo * GATES + n], Ub[(size_t)(k_lo + 1) * GATES + n]);
    }
}

// ---------------- fused bf16 tensor-core LSTM recurrence ----------------
// grid (64, 2), block 512. Reads fp16 zx; writes fp32 h (for combine/output)
// and bf16x2 h (A operand for the next layer's gemm).
__global__ __launch_bounds__(512) void lstm_tc(
    const __half* __restrict__ zx_fw, const __half* __restrict__ zx_bw,
    const uint32_t* __restrict__ uf_fw, const uint32_t* __restrict__ uf_bw,
    float* __restrict__ out_fw, float* __restrict__ out_bw,
    uint32_t* __restrict__ hb_fw, uint32_t* __restrict__ hb_bw)
{
    const int dir = blockIdx.y;
    const __half* __restrict__ zx = dir ? zx_bw : zx_fw;
    const uint32_t* __restrict__ uf = dir ? uf_bw : uf_fw;
    float* __restrict__ out = dir ? out_bw : out_fw;
    uint32_t* __restrict__ hb = dir ? hb_bw : hb_fw;

    const int b0  = blockIdx.x * 8;
    const int tid = threadIdx.x;
    const int w   = tid >> 5;
    const int lane = tid & 31;
    const int g = lane >> 2;
    const int tig = lane & 3;
    const int col0 = 8 * w + 2 * tig;

    __shared__ __align__(16) uint32_t h2[2][16][68];

    for (int q2 = tid; q2 < 2 * 16 * 68; q2 += 512) ((uint32_t*)h2)[q2] = 0u;
    float c0 = 0.f, c1 = 0.f;

    const uint4* ufp[4];
#pragma unroll
    for (int nt = 0; nt < 4; nt++)
        ufp[nt] = (const uint4*)uf + (size_t)(w + 16 * nt) * 4 * 32 + lane;

    const __half* zr0 = zx + ((size_t)(b0 + g) * SEQT) * GATES + col0;
    float* or0 = out + ((size_t)(b0 + g) * SEQT) * HID + col0;
    uint32_t* hr0 = hb + (((size_t)(b0 + g) * SEQT) * HID + col0) / 2;

    __syncthreads();

    for (int s = 0; s < SEQT; s++) {
        const int t = dir ? (SEQT - 1 - s) : s;
        const int rb = s & 1;
        const int wb = rb ^ 1;

        float2 zv0[4];
#pragma unroll
        for (int nt = 0; nt < 4; nt++) {
            __half2 hz = *(const __half2*)&zr0[(size_t)t * GATES + 128 * nt];
            zv0[nt] = __half22float2(hz);
        }

        float acc[4][4];
#pragma unroll
        for (int nt = 0; nt < 4; nt++)
#pragma unroll
            for (int q = 0; q < 4; q++) acc[nt][q] = 0.f;

        uint4 bv[4];
#pragma unroll
        for (int nt = 0; nt < 4; nt++) bv[nt] = ufp[nt][0];

#pragma unroll
        for (int kt2 = 0; kt2 < 4; kt2++) {
            uint4 nb[4];
            if (kt2 < 3) {
#pragma unroll
                for (int nt = 0; nt < 4; nt++) nb[nt] = ufp[nt][(kt2 + 1) * 32];
            }
            const int kbe = kt2 * 16;
            uint32_t ae[4], ao[4];
            ae[0] = h2[rb][g][kbe + tig];
            ae[1] = h2[rb][g + 8][kbe + tig];
            ae[2] = h2[rb][g][kbe + tig + 4];
            ae[3] = h2[rb][g + 8][kbe + tig + 4];
            ao[0] = h2[rb][g][kbe + 8 + tig];
            ao[1] = h2[rb][g + 8][kbe + 8 + tig];
            ao[2] = h2[rb][g][kbe + 8 + tig + 4];
            ao[3] = h2[rb][g + 8][kbe + 8 + tig + 4];
#pragma unroll
            for (int nt = 0; nt < 4; nt++) {
                mma_bf16(acc[nt], ae, bv[nt].x, bv[nt].y);
                mma_bf16(acc[nt], ao, bv[nt].z, bv[nt].w);
            }
#pragma unroll
            for (int nt = 0; nt < 4; nt++) bv[nt] = nb[nt];
        }

        float h00, h01;
        {
            float ig = sigm(acc[0][0] + zv0[0].x), fg = sigm(acc[1][0] + zv0[1].x);
            float gg = tanh_(acc[2][0] + zv0[2].x), og = sigm(acc[3][0] + zv0[3].x);
            c0 = fg * c0 + ig * gg;  h00 = og * tanh_(c0);
        }
        {
            float ig = sigm(acc[0][1] + zv0[0].y), fg = sigm(acc[1][1] + zv0[1].y);
            float gg = tanh_(acc[2][1] + zv0[2].y), og = sigm(acc[3][1] + zv0[3].y);
            c1 = fg * c1 + ig * gg;  h01 = og * tanh_(c1);
        }

        uint32_t hp = bf2(h00, h01);
        h2[wb][g][col0 >> 1] = hp;
        hr0[(size_t)t * (HID/2)] = hp;
        *(float2*)&or0[(size_t)t * HID] = make_float2(h00, h01);

        __syncthreads();
    }
}

// ---------------- final combine ----------------
__global__ void combine(const float* __restrict__ a, const float* __restrict__ b,
                        const float* __restrict__ c, const float* __restrict__ d,
                        float* __restrict__ out, int n4)
{
    int i = blockIdx.x * blockDim.x + threadIdx.x;
    if (i < n4) {
        float4 va = ((const float4*)a)[i];
        float4 vb = ((const float4*)b)[i];
        float4 vc = ((const float4*)c)[i];
        float4 vd = ((const float4*)d)[i];
        float4 o;
        o.x = 0.5f * (va.x + vb.x + vc.x + vd.x);
        o.y = 0.5f * (va.y + vb.y + vc.y + vd.y);
        o.z = 0.5f * (va.z + vb.z + vc.z + vd.z);
        o.w = 0.5f * (va.w + vb.w + vc.w + vd.w);
        ((float4*)out)[i] = o;
    }
}

// ---------------- launch ----------------
extern "C" void kernel_launch(void* const* d_in, const int* in_sizes, int n_in,
                              void* d_out, int out_size)
{
    const float* x = (const float*)d_in[0];
    const float* W = (const float*)d_in[1];
    const float* U = (const float*)d_in[2];
    const float* b = (const float*)d_in[3];

    __half *zxf, *zxb;
    float *s0f, *s0b, *s1f, *s1b;
    uint32_t *xb, *hb0f, *hb0b, *Wtb, *UFB;
    cudaGetSymbolAddress((void**)&zxf, g_zx_fw);
    cudaGetSymbolAddress((void**)&zxb, g_zx_bw);
    cudaGetSymbolAddress((void**)&s0f, g_s0f);
    cudaGetSymbolAddress((void**)&s0b, g_s0b);
    cudaGetSymbolAddress((void**)&s1f, g_s1f);
    cudaGetSymbolAddress((void**)&s1b, g_s1b);
    cudaGetSymbolAddress((void**)&xb, g_xb);
    cudaGetSymbolAddress((void**)&hb0f, g_hb0f);
    cudaGetSymbolAddress((void**)&hb0b, g_hb0b);
    cudaGetSymbolAddress((void**)&Wtb, g_Wtb);
    cudaGetSymbolAddress((void**)&UFB, g_UfragB);

    cudaFuncSetAttribute(gemm_bf, cudaFuncAttributeMaxDynamicSharedMemorySize, GSMEM);

    const size_t WBSZ = (size_t)GATES * (EMB/2);   // 32768 uint32
    const size_t UFSZ = 64 * 4 * 32 * 4;           // 32768 uint32
    const float* b00 = b;           const float* b01 = b + GATES;
    const float* b10 = b + 2*GATES; const float* b11 = b + 3*GATES;
    uint32_t* Wt00 = Wtb;            uint32_t* Wt01 = Wtb + WBSZ;
    uint32_t* Wt10 = Wtb + 2*WBSZ;   uint32_t* Wt11 = Wtb + 3*WBSZ;
    uint32_t* UF00 = UFB;            uint32_t* UF01 = UFB + UFSZ;
    uint32_t* UF10 = UFB + 2*UFSZ;   uint32_t* UF11 = UFB + 3*UFSZ;

    int nx2 = MTOT * EMB / 2;
    convert_x<<<(nx2 + 255) / 256, 256>>>(x, xb, nx2);
    build_wtb<<<(4 * GATES * (EMB/2) + 255) / 256, 256>>>(W, Wtb);
    build_ufragb<<<(4 * 64 * 4 * 32 * 4 + 255) / 256, 256>>>(U, UFB);

    dim3 gg(GATES / 128, MTOT / 128);   // (4, 800) = 3200 blocks
    dim3 lg(BATCH / 8, 2);              // (64, 2)

    gemm_bf<<<gg, 256, GSMEM>>>(xb, Wt00, b00, zxf);
    gemm_bf<<<gg, 256, GSMEM>>>(xb, Wt01, b01, zxb);
    lstm_tc<<<lg, 512>>>(zxf, zxb, UF00, UF01, s0f, s0b, hb0f, hb0b);

    gemm_bf<<<gg, 256, GSMEM>>>(hb0f, Wt10, b10, zxf);
    gemm_bf<<<gg, 256, GSMEM>>>(hb0b, Wt11, b11, zxb);
    // layer-1 lstm: bf16 h sink reuses hb0f/hb0b (already consumed)
    lstm_tc<<<lg, 512>>>(zxf, zxb, UF10, UF11, s1f, s1b, hb0f, hb0b);

    int n4 = MTOT * HID / 4;
    combine<<<(n4 + 255) / 256, 256>>>(s1f, s0f, s1b, s0b, (float*)d_out, n4);
}

// round 13
// speedup vs baseline: 1.0900x; 1.0044x over previous
#include <cuda_runtime.h>
#include <cuda_bf16.h>
#include <cuda_fp16.h>
#include <math.h>
#include <stdint.h>

#define BATCH 512
#define SEQT  200
#define HID   128
#define GATES 512   // 4H
#define EMB   128
#define MTOT  (BATCH*SEQT)   // 102400

// ---------------- static scratch ----------------
__device__ __half g_zx_fw[(size_t)MTOT * GATES];     // fp16 zx
__device__ __half g_zx_bw[(size_t)MTOT * GATES];
__device__ float g_s0f[(size_t)MTOT * HID];
__device__ float g_s0b[(size_t)MTOT * HID];
__device__ float g_s1f[(size_t)MTOT * HID];
__device__ float g_s1b[(size_t)MTOT * HID];
__device__ uint32_t g_xb[(size_t)MTOT * EMB / 2];    // bf16x2 x
__device__ uint32_t g_hb0f[(size_t)MTOT * HID / 2];  // bf16x2 h (fw)
__device__ uint32_t g_hb0b[(size_t)MTOT * HID / 2];  // bf16x2 h (bw)
__device__ uint32_t g_Wtb[4 * GATES * (EMB/2)];      // bf16x2 W^T: [4][n=512][k2=64]
__device__ uint32_t g_UfragB[4 * 64 * 4 * 32 * 4];   // bf16 U fragments (m16n8k16)

// ---------------- helpers ----------------
__device__ __forceinline__ float rcp_(float x) {
    float y; asm("rcp.approx.f32 %0, %1;" : "=f"(y) : "f"(x)); return y;
}
__device__ __forceinline__ float ex2_(float x) {
    float y; asm("ex2.approx.f32 %0, %1;" : "=f"(y) : "f"(x)); return y;
}
__device__ __forceinline__ float sigm(float x) {
    return rcp_(1.f + ex2_(-1.4426950408889634f * x));
}
__device__ __forceinline__ float tanh_(float x) {
    return 1.f - 2.f * rcp_(1.f + ex2_(2.8853900817779268f * x));
}
__device__ __forceinline__ uint32_t bf2(float lo, float hi) {
    __nv_bfloat162 v = __floats2bfloat162_rn(lo, hi);
    return *(uint32_t*)&v;
}
__device__ __forceinline__ uint32_t smem_u32(const void* p) {
    uint32_t a;
    asm("{ .reg .u64 t; cvta.to.shared.u64 t, %1; cvt.u32.u64 %0, t; }" : "=r"(a) : "l"(p));
    return a;
}
__device__ __forceinline__ void cp16(uint32_t s, const void* g) {
    asm volatile("cp.async.cg.shared.global [%0], [%1], 16;" :: "r"(s), "l"(g));
}
__device__ __forceinline__ void ldsm4(uint32_t& d0, uint32_t& d1, uint32_t& d2, uint32_t& d3,
                                      uint32_t addr) {
    asm volatile("ldmatrix.sync.aligned.m8n8.x4.shared.b16 {%0,%1,%2,%3}, [%4];"
        : "=r"(d0), "=r"(d1), "=r"(d2), "=r"(d3) : "r"(addr));
}

__device__ __forceinline__ void mma_bf16(float* d, const uint32_t* a, uint32_t b0, uint32_t b1) {
    asm volatile(
        "mma.sync.aligned.m16n8k16.row.col.f32.bf16.bf16.f32 "
        "{%0,%1,%2,%3}, {%4,%5,%6,%7}, {%8,%9}, {%0,%1,%2,%3};"
        : "+f"(d[0]), "+f"(d[1]), "+f"(d[2]), "+f"(d[3])
        : "r"(a[0]), "r"(a[1]), "r"(a[2]), "r"(a[3]), "r"(b0), "r"(b1));
}

// ---------------- bf16 GEMM: C[m,n] = A[m,k] @ Wt[n,k]^T + bias[n], C fp16 ----------------
// A bf16x2 [MTOT][64]. Tile M=128,N=128,K=128 single pass; cp.async staging; ldmatrix fragments.
#define LDB2 68
#define TILE_STRIDE (16 * LDB2 * 4)   // bytes between 16-row groups
#define GSMEM (2 * 128 * LDB2 * 4)    // ~68KB

__global__ __launch_bounds__(256, 2) void gemm_bf(
    const uint32_t* __restrict__ A2, const uint32_t* __restrict__ Wtb,
    const float* __restrict__ bias, __half* __restrict__ C)
{
    extern __shared__ __align__(16) char smem[];
    uint32_t (*As2)[LDB2] = (uint32_t(*)[LDB2])smem;                         // [128][68]
    uint32_t (*Bs2)[LDB2] = (uint32_t(*)[LDB2])(smem + 128 * LDB2 * 4);      // [128][68]

    const int tid = threadIdx.x;
    const int wid = tid >> 5;
    const int lane = tid & 31;
    const int wm = wid & 1;
    const int wn = wid >> 1;
    const int g = lane >> 2;
    const int tig = lane & 3;

    const size_t m0 = (size_t)blockIdx.y * 128;
    const int n0 = blockIdx.x * 128;

    // stage A and B via cp.async
#pragma unroll
    for (int i = 0; i < 8; i++) {
        int idx = tid + i * 256;       // 0..2047
        int row = idx >> 4;
        int c4  = idx & 15;
        cp16(smem_u32(&As2[row][c4 * 4]), A2 + (m0 + row) * (EMB/2) + c4 * 4);
        cp16(smem_u32(&Bs2[row][c4 * 4]), Wtb + (size_t)(n0 + row) * (EMB/2) + c4 * 4);
    }
    asm volatile("cp.async.commit_group;");
    asm volatile("cp.async.wait_group 0;" ::: "memory");
    __syncthreads();

    // ldmatrix base addresses
    // A: row = wm*64 + (lane&15) (+ mt*16 via offset), coladd = (lane>>4)*4 uint32
    const uint32_t a_base = smem_u32(&As2[wm * 64 + (lane & 15)][(lane >> 4) * 4]);
    // B: row = wn*32 + ((lane>>4)&1)*8 + (lane&7) (+ pair*16), coladd = ((lane>>3)&1)*4
    const uint32_t b_base = smem_u32(&Bs2[wn * 32 + ((lane >> 4) & 1) * 8 + (lane & 7)]
                                        [((lane >> 3) & 1) * 4]);

    float acc[4][4][4];
#pragma unroll
    for (int mt = 0; mt < 4; mt++)
#pragma unroll
        for (int nt = 0; nt < 4; nt++)
#pragma unroll
            for (int q = 0; q < 4; q++) acc[mt][nt][q] = 0.f;

#pragma unroll
    for (int k8 = 0; k8 < 8; k8++) {
        const uint32_t koff = k8 * 32;   // 8 uint32 = 32 bytes per k8
        uint32_t af[4][4];
#pragma unroll
        for (int mt = 0; mt < 4; mt++)
            ldsm4(af[mt][0], af[mt][1], af[mt][2], af[mt][3],
                  a_base + mt * TILE_STRIDE + koff);
        uint32_t bf[4][2];
        ldsm4(bf[0][0], bf[0][1], bf[1][0], bf[1][1], b_base + koff);
        ldsm4(bf[2][0], bf[2][1], bf[3][0], bf[3][1], b_base + TILE_STRIDE + koff);
#pragma unroll
        for (int nt = 0; nt < 4; nt++)
#pragma unroll
            for (int mt = 0; mt < 4; mt++)
                mma_bf16(acc[mt][nt], af[mt], bf[nt][0], bf[nt][1]);
    }

#pragma unroll
    for (int nt = 0; nt < 4; nt++) {
        int col = n0 + wn * 32 + nt * 8 + 2 * tig;
        float b0 = bias[col], b1 = bias[col + 1];
#pragma unroll
        for (int mt = 0; mt < 4; mt++) {
            size_t row = m0 + wm * 64 + mt * 16 + g;
            __half2 o0 = __floats2half2_rn(acc[mt][nt][0] + b0, acc[mt][nt][1] + b1);
            __half2 o1 = __floats2half2_rn(acc[mt][nt][2] + b0, acc[mt][nt][3] + b1);
            *(__half2*)&C[row * GATES + col] = o0;
            *(__half2*)&C[(row + 8) * GATES + col] = o1;
        }
    }
}

// ---------------- x -> bf16x2 ----------------
__global__ void convert_x(const float* __restrict__ x, uint32_t* __restrict__ xb, int n2)
{
    int i = blockIdx.x * blockDim.x + threadIdx.x;
    if (i < n2) {
        float2 v = ((const float2*)x)[i];
        xb[i] = bf2(v.x, v.y);
    }
}

// ---------------- W -> bf16x2 transposed ----------------
__global__ void build_wtb(const float* __restrict__ W, uint32_t* __restrict__ Wtb)
{
    int idx = blockIdx.x * blockDim.x + threadIdx.x;
    if (idx < 4 * GATES * (EMB/2)) {
        int k2 = idx & 63;
        int n  = (idx >> 6) & 511;
        int u  = idx >> 15;
        const float* Wb = W + (size_t)u * (EMB * GATES);
        Wtb[idx] = bf2(Wb[(size_t)(2*k2) * GATES + n], Wb[(size_t)(2*k2+1) * GATES + n]);
    }
}

// ---------------- bf16 U fragment pre-swizzle ----------------
__global__ void build_ufragb(const float* __restrict__ U, uint32_t* __restrict__ UFB)
{
    int idx = blockIdx.x * blockDim.x + threadIdx.x;
    if (idx < 4 * 64 * 4 * 32 * 4) {
        int q    = idx & 3;
        int lane = (idx >> 2) & 31;
        int kt2  = (idx >> 7) & 3;
        int ntg  = (idx >> 9) & 63;
        int u    = idx >> 15;
        int tig = lane & 3, gg = lane >> 2;
        int kt  = kt2 * 2 + (q >> 1);
        int reg = q & 1;
        int k_lo = kt * 16 + reg * 8 + 2 * tig;
        int n = ntg * 8 + gg;
        const float* Ub = U + (size_t)u * (EMB * GATES);
        UFB[idx] = bf2(Ub[(size_t)k_lo * GATES + n], Ub[(size_t)(k_lo + 1) * GATES + n]);
    }
}

// ---------------- fused bf16 tensor-core LSTM recurrence ----------------
// grid (64, 2), block 512. ldmatrix for h fragments; fp16 zx; bf16x2 + fp32 h outputs.
__global__ __launch_bounds__(512) void lstm_tc(
    const __half* __restrict__ zx_fw, const __half* __restrict__ zx_bw,
    const uint32_t* __restrict__ uf_fw, const uint32_t* __restrict__ uf_bw,
    float* __restrict__ out_fw, float* __restrict__ out_bw,
    uint32_t* __restrict__ hb_fw, uint32_t* __restrict__ hb_bw)
{
    const int dir = blockIdx.y;
    const __half* __restrict__ zx = dir ? zx_bw : zx_fw;
    const uint32_t* __restrict__ uf = dir ? uf_bw : uf_fw;
    float* __restrict__ out = dir ? out_bw : out_fw;
    uint32_t* __restrict__ hb = dir ? hb_bw : hb_fw;

    const int b0  = blockIdx.x * 8;
    const int tid = threadIdx.x;
    const int w   = tid >> 5;
    const int lane = tid & 31;
    const int g = lane >> 2;
    const int tig = lane & 3;
    const int col0 = 8 * w + 2 * tig;

    __shared__ __align__(16) uint32_t h2[2][16][68];

    for (int q2 = tid; q2 < 2 * 16 * 68; q2 += 512) ((uint32_t*)h2)[q2] = 0u;
    float c0 = 0.f, c1 = 0.f;

    const uint4* ufp[4];
#pragma unroll
    for (int nt = 0; nt < 4; nt++)
        ufp[nt] = (const uint4*)uf + (size_t)(w + 16 * nt) * 4 * 32 + lane;

    // ldmatrix base addresses for the two h ping-pong buffers
    uint32_t h_base[2];
#pragma unroll
    for (int rb2 = 0; rb2 < 2; rb2++)
        h_base[rb2] = smem_u32(&h2[rb2][lane & 15][(lane >> 4) * 4]);

    const __half* zr0 = zx + ((size_t)(b0 + g) * SEQT) * GATES + col0;
    float* or0 = out + ((size_t)(b0 + g) * SEQT) * HID + col0;
    uint32_t* hr0 = hb + (((size_t)(b0 + g) * SEQT) * HID + col0) / 2;

    __syncthreads();

    for (int s = 0; s < SEQT; s++) {
        const int t = dir ? (SEQT - 1 - s) : s;
        const int rb = s & 1;
        const int wb = rb ^ 1;

        float2 zv0[4];
#pragma unroll
        for (int nt = 0; nt < 4; nt++) {
            __half2 hz = *(const __half2*)&zr0[(size_t)t * GATES + 128 * nt];
            zv0[nt] = __half22float2(hz);
        }

        float acc[4][4];
#pragma unroll
        for (int nt = 0; nt < 4; nt++)
#pragma unroll
            for (int q = 0; q < 4; q++) acc[nt][q] = 0.f;

        uint4 bv[4];
#pragma unroll
        for (int nt = 0; nt < 4; nt++) bv[nt] = ufp[nt][0];

#pragma unroll
        for (int kt2 = 0; kt2 < 4; kt2++) {
            uint4 nb[4];
            if (kt2 < 3) {
#pragma unroll
                for (int nt = 0; nt < 4; nt++) nb[nt] = ufp[nt][(kt2 + 1) * 32];
            }
            uint32_t ae[4], ao[4];
            ldsm4(ae[0], ae[1], ae[2], ae[3], h_base[rb] + kt2 * 64);
            ldsm4(ao[0], ao[1], ao[2], ao[3], h_base[rb] + kt2 * 64 + 32);
#pragma unroll
            for (int nt = 0; nt < 4; nt++) {
                mma_bf16(acc[nt], ae, bv[nt].x, bv[nt].y);
                mma_bf16(acc[nt], ao, bv[nt].z, bv[nt].w);
            }
#pragma unroll
            for (int nt = 0; nt < 4; nt++) bv[nt] = nb[nt];
        }

        float h00, h01;
        {
            float ig = sigm(acc[0][0] + zv0[0].x), fg = sigm(acc[1][0] + zv0[1].x);
            float gg = tanh_(acc[2][0] + zv0[2].x), og = sigm(acc[3][0] + zv0[3].x);
            c0 = fg * c0 + ig * gg;  h00 = og * tanh_(c0);
        }
        {
            float ig = sigm(acc[0][1] + zv0[0].y), fg = sigm(acc[1][1] + zv0[1].y);
            float gg = tanh_(acc[2][1] + zv0[2].y), og = sigm(acc[3][1] + zv0[3].y);
            c1 = fg * c1 + ig * gg;  h01 = og * tanh_(c1);
        }

        uint32_t hp = bf2(h00, h01);
        h2[wb][g][col0 >> 1] = hp;
        hr0[(size_t)t * (HID/2)] = hp;
        *(float2*)&or0[(size_t)t * HID] = make_float2(h00, h01);

        __syncthreads();
    }
}

// ---------------- final combine ----------------
__global__ void combine(const float* __restrict__ a, const float* __restrict__ b,
                        const float* __restrict__ c, const float* __restrict__ d,
                        float* __restrict__ out, int n4)
{
    int i = blockIdx.x * blockDim.x + threadIdx.x;
    if (i < n4) {
        float4 va = ((const float4*)a)[i];
        float4 vb = ((const float4*)b)[i];
        float4 vc = ((const float4*)c)[i];
        float4 vd = ((const float4*)d)[i];
        float4 o;
        o.x = 0.5f * (va.x + vb.x + vc.x + vd.x);
        o.y = 0.5f * (va.y + vb.y + vc.y + vd.y);
        o.z = 0.5f * (va.z + vb.z + vc.z + vd.z);
        o.w = 0.5f * (va.w + vb.w + vc.w + vd.w);
        ((float4*)out)[i] = o;
    }
}

// ---------------- launch ----------------
extern "C" void kernel_launch(void* const* d_in, const int* in_sizes, int n_in,
                              void* d_out, int out_size)
{
    const float* x = (const float*)d_in[0];
    const float* W = (const float*)d_in[1];
    const float* U = (const float*)d_in[2];
    const float* b = (const float*)d_in[3];

    __half *zxf, *zxb;
    float *s0f, *s0b, *s1f, *s1b;
    uint32_t *xb, *hb0f, *hb0b, *Wtb, *UFB;
    cudaGetSymbolAddress((void**)&zxf, g_zx_fw);
    cudaGetSymbolAddress((void**)&zxb, g_zx_bw);
    cudaGetSymbolAddress((void**)&s0f, g_s0f);
    cudaGetSymbolAddress((void**)&s0b, g_s0b);
    cudaGetSymbolAddress((void**)&s1f, g_s1f);
    cudaGetSymbolAddress((void**)&s1b, g_s1b);
    cudaGetSymbolAddress((void**)&xb, g_xb);
    cudaGetSymbolAddress((void**)&hb0f, g_hb0f);
    cudaGetSymbolAddress((void**)&hb0b, g_hb0b);
    cudaGetSymbolAddress((void**)&Wtb, g_Wtb);
    cudaGetSymbolAddress((void**)&UFB, g_UfragB);

    cudaFuncSetAttribute(gemm_bf, cudaFuncAttributeMaxDynamicSharedMemorySize, GSMEM);

    const size_t WBSZ = (size_t)GATES * (EMB/2);   // 32768 uint32
    const size_t UFSZ = 64 * 4 * 32 * 4;           // 32768 uint32
    const float* b00 = b;           const float* b01 = b + GATES;
    const float* b10 = b + 2*GATES; const float* b11 = b + 3*GATES;
    uint32_t* Wt00 = Wtb;            uint32_t* Wt01 = Wtb + WBSZ;
    uint32_t* Wt10 = Wtb + 2*WBSZ;   uint32_t* Wt11 = Wtb + 3*WBSZ;
    uint32_t* UF00 = UFB;            uint32_t* UF01 = UFB + UFSZ;
    uint32_t* UF10 = UFB + 2*UFSZ;   uint32_t* UF11 = UFB + 3*UFSZ;

    int nx2 = MTOT * EMB / 2;
    convert_x<<<(nx2 + 255) / 256, 256>>>(x, xb, nx2);
    build_wtb<<<(4 * GATES * (EMB/2) + 255) / 256, 256>>>(W, Wtb);
    build_ufragb<<<(4 * 64 * 4 * 32 * 4 + 255) / 256, 256>>>(U, UFB);

    dim3 gg(GATES / 128, MTOT / 128);   // (4, 800)
    dim3 lg(BATCH / 8, 2);              // (64, 2)

    gemm_bf<<<gg, 256, GSMEM>>>(xb, Wt00, b00, zxf);
    gemm_bf<<<gg, 256, GSMEM>>>(xb, Wt01, b01, zxb);
    lstm_tc<<<lg, 512>>>(zxf, zxb, UF00, UF01, s0f, s0b, hb0f, hb0b);

    gemm_bf<<<gg, 256, GSMEM>>>(hb0f, Wt10, b10, zxf);
    gemm_bf<<<gg, 256, GSMEM>>>(hb0b, Wt11, b11, zxb);
    lstm_tc<<<lg, 512>>>(zxf, zxb, UF10, UF11, s1f, s1b, hb0f, hb0b);

    int n4 = MTOT * HID / 4;
    combine<<<(n4 + 255) / 256, 256>>>(s1f, s0f, s1b, s0b, (float*)d_out, n4);
}

// round 14
// speedup vs baseline: 1.1156x; 1.0234x over previous
#include <cuda_runtime.h>
#include <cuda_bf16.h>
#include <cuda_fp16.h>
#include <math.h>
#include <stdint.h>

#define BATCH 512
#define SEQT  200
#define HID   128
#define GATES 512   // 4H
#define EMB   128
#define MTOT  (BATCH*SEQT)   // 102400

// ---------------- static scratch ----------------
__device__ __half g_zx_fw[(size_t)MTOT * GATES];     // fp16 zx
__device__ __half g_zx_bw[(size_t)MTOT * GATES];
__device__ float g_s0f[(size_t)MTOT * HID];
__device__ float g_s0b[(size_t)MTOT * HID];
__device__ float g_s1f[(size_t)MTOT * HID];
__device__ float g_s1b[(size_t)MTOT * HID];
__device__ uint32_t g_xb[(size_t)MTOT * EMB / 2];    // bf16x2 x
__device__ uint32_t g_hb0f[(size_t)MTOT * HID / 2];  // bf16x2 h (fw)
__device__ uint32_t g_hb0b[(size_t)MTOT * HID / 2];  // bf16x2 h (bw)
__device__ uint32_t g_Wtb[4 * GATES * (EMB/2)];      // bf16x2 W^T: [4][n=512][k2=64]
__device__ uint32_t g_UfragB[4 * 64 * 4 * 32 * 4];   // bf16 U fragments (m16n8k16)

// ---------------- helpers ----------------
__device__ __forceinline__ float rcp_(float x) {
    float y; asm("rcp.approx.f32 %0, %1;" : "=f"(y) : "f"(x)); return y;
}
__device__ __forceinline__ float ex2_(float x) {
    float y; asm("ex2.approx.f32 %0, %1;" : "=f"(y) : "f"(x)); return y;
}
__device__ __forceinline__ float sigm(float x) {
    return rcp_(1.f + ex2_(-1.4426950408889634f * x));
}
__device__ __forceinline__ float tanh_(float x) {
    return 1.f - 2.f * rcp_(1.f + ex2_(2.8853900817779268f * x));
}
__device__ __forceinline__ uint32_t bf2(float lo, float hi) {
    __nv_bfloat162 v = __floats2bfloat162_rn(lo, hi);
    return *(uint32_t*)&v;
}
__device__ __forceinline__ uint32_t smem_u32(const void* p) {
    uint32_t a;
    asm("{ .reg .u64 t; cvta.to.shared.u64 t, %1; cvt.u32.u64 %0, t; }" : "=r"(a) : "l"(p));
    return a;
}
__device__ __forceinline__ void cp16(uint32_t s, const void* g) {
    asm volatile("cp.async.cg.shared.global [%0], [%1], 16;" :: "r"(s), "l"(g));
}
__device__ __forceinline__ void ldsm4(uint32_t& d0, uint32_t& d1, uint32_t& d2, uint32_t& d3,
                                      uint32_t addr) {
    asm volatile("ldmatrix.sync.aligned.m8n8.x4.shared.b16 {%0,%1,%2,%3}, [%4];"
        : "=r"(d0), "=r"(d1), "=r"(d2), "=r"(d3) : "r"(addr));
}

__device__ __forceinline__ void mma_bf16(float* d, const uint32_t* a, uint32_t b0, uint32_t b1) {
    asm volatile(
        "mma.sync.aligned.m16n8k16.row.col.f32.bf16.bf16.f32 "
        "{%0,%1,%2,%3}, {%4,%5,%6,%7}, {%8,%9}, {%0,%1,%2,%3};"
        : "+f"(d[0]), "+f"(d[1]), "+f"(d[2]), "+f"(d[3])
        : "r"(a[0]), "r"(a[1]), "r"(a[2]), "r"(a[3]), "r"(b0), "r"(b1));
}

// ---------------- bf16 GEMM: C[m,n] = A[m,k] @ Wt[n,k]^T + bias[n], C fp16 ----------------
// Tile M=128,N=128,K=128; 2-stage cp.async k-pipeline; ldmatrix fragments.
// blockIdx.z selects direction (fw/bw pair fused into one launch).
#define LDB2 68
#define TILE_STRIDE (16 * LDB2 * 4)   // bytes between 16-row groups
#define GSMEM (2 * 128 * LDB2 * 4)    // ~68KB

__global__ __launch_bounds__(256, 2) void gemm_bf(
    const uint32_t* __restrict__ a_fw, const uint32_t* __restrict__ a_bw,
    const uint32_t* __restrict__ w_fw, const uint32_t* __restrict__ w_bw,
    const float* __restrict__ bias_fw, const float* __restrict__ bias_bw,
    __half* __restrict__ c_fw, __half* __restrict__ c_bw)
{
    const int dir = blockIdx.z;
    const uint32_t* __restrict__ A2  = dir ? a_bw : a_fw;
    const uint32_t* __restrict__ Wtb = dir ? w_bw : w_fw;
    const float* __restrict__ bias   = dir ? bias_bw : bias_fw;
    __half* __restrict__ C           = dir ? c_bw : c_fw;

    extern __shared__ __align__(16) char smem[];
    uint32_t (*As2)[LDB2] = (uint32_t(*)[LDB2])smem;                         // [128][68]
    uint32_t (*Bs2)[LDB2] = (uint32_t(*)[LDB2])(smem + 128 * LDB2 * 4);      // [128][68]

    const int tid = threadIdx.x;
    const int wid = tid >> 5;
    const int lane = tid & 31;
    const int wm = wid & 1;
    const int wn = wid >> 1;
    const int g = lane >> 2;
    const int tig = lane & 3;

    const size_t m0 = (size_t)blockIdx.y * 128;
    const int n0 = blockIdx.x * 128;

    // stage k-half 0 (cols 0..31), then k-half 1 (cols 32..63), separate groups
#pragma unroll
    for (int h = 0; h < 2; h++) {
#pragma unroll
        for (int i = 0; i < 4; i++) {
            int idx = tid + i * 256;       // 0..1023
            int row = idx >> 3;            // 0..127
            int c4  = (idx & 7) + h * 8;   // chunk index 0..15
            cp16(smem_u32(&As2[row][c4 * 4]), A2 + (m0 + row) * (EMB/2) + c4 * 4);
            cp16(smem_u32(&Bs2[row][c4 * 4]), Wtb + (size_t)(n0 + row) * (EMB/2) + c4 * 4);
        }
        asm volatile("cp.async.commit_group;");
    }

    // ldmatrix base addresses
    const uint32_t a_base = smem_u32(&As2[wm * 64 + (lane & 15)][(lane >> 4) * 4]);
    const uint32_t b_base = smem_u32(&Bs2[wn * 32 + ((lane >> 4) & 1) * 8 + (lane & 7)]
                                        [((lane >> 3) & 1) * 4]);

    float acc[4][4][4];
#pragma unroll
    for (int mt = 0; mt < 4; mt++)
#pragma unroll
        for (int nt = 0; nt < 4; nt++)
#pragma unroll
            for (int q = 0; q < 4; q++) acc[mt][nt][q] = 0.f;

    asm volatile("cp.async.wait_group 1;" ::: "memory");
    __syncthreads();

    // mma on k-half 0 while half 1 is still in flight
#pragma unroll
    for (int k8 = 0; k8 < 4; k8++) {
        const uint32_t koff = k8 * 32;
        uint32_t af[4][4];
#pragma unroll
        for (int mt = 0; mt < 4; mt++)
            ldsm4(af[mt][0], af[mt][1], af[mt][2], af[mt][3],
                  a_base + mt * TILE_STRIDE + koff);
        uint32_t bf[4][2];
        ldsm4(bf[0][0], bf[0][1], bf[1][0], bf[1][1], b_base + koff);
        ldsm4(bf[2][0], bf[2][1], bf[3][0], bf[3][1], b_base + TILE_STRIDE + koff);
#pragma unroll
        for (int nt = 0; nt < 4; nt++)
#pragma unroll
            for (int mt = 0; mt < 4; mt++)
                mma_bf16(acc[mt][nt], af[mt], bf[nt][0], bf[nt][1]);
    }

    asm volatile("cp.async.wait_group 0;" ::: "memory");
    __syncthreads();

#pragma unroll
    for (int k8 = 4; k8 < 8; k8++) {
        const uint32_t koff = k8 * 32;
        uint32_t af[4][4];
#pragma unroll
        for (int mt = 0; mt < 4; mt++)
            ldsm4(af[mt][0], af[mt][1], af[mt][2], af[mt][3],
                  a_base + mt * TILE_STRIDE + koff);
        uint32_t bf[4][2];
        ldsm4(bf[0][0], bf[0][1], bf[1][0], bf[1][1], b_base + koff);
        ldsm4(bf[2][0], bf[2][1], bf[3][0], bf[3][1], b_base + TILE_STRIDE + koff);
#pragma unroll
        for (int nt = 0; nt < 4; nt++)
#pragma unroll
            for (int mt = 0; mt < 4; mt++)
                mma_bf16(acc[mt][nt], af[mt], bf[nt][0], bf[nt][1]);
    }

#pragma unroll
    for (int nt = 0; nt < 4; nt++) {
        int col = n0 + wn * 32 + nt * 8 + 2 * tig;
        float b0 = bias[col], b1 = bias[col + 1];
#pragma unroll
        for (int mt = 0; mt < 4; mt++) {
            size_t row = m0 + wm * 64 + mt * 16 + g;
            __half2 o0 = __floats2half2_rn(acc[mt][nt][0] + b0, acc[mt][nt][1] + b1);
            __half2 o1 = __floats2half2_rn(acc[mt][nt][2] + b0, acc[mt][nt][3] + b1);
            *(__half2*)&C[row * GATES + col] = o0;
            *(__half2*)&C[(row + 8) * GATES + col] = o1;
        }
    }
}

// ---------------- x -> bf16x2 ----------------
__global__ void convert_x(const float* __restrict__ x, uint32_t* __restrict__ xb, int n2)
{
    int i = blockIdx.x * blockDim.x + threadIdx.x;
    if (i < n2) {
        float2 v = ((const float2*)x)[i];
        xb[i] = bf2(v.x, v.y);
    }
}

// ---------------- W -> bf16x2 transposed ----------------
__global__ void build_wtb(const float* __restrict__ W, uint32_t* __restrict__ Wtb)
{
    int idx = blockIdx.x * blockDim.x + threadIdx.x;
    if (idx < 4 * GATES * (EMB/2)) {
        int k2 = idx & 63;
        int n  = (idx >> 6) & 511;
        int u  = idx >> 15;
        const float* Wb = W + (size_t)u * (EMB * GATES);
        Wtb[idx] = bf2(Wb[(size_t)(2*k2) * GATES + n], Wb[(size_t)(2*k2+1) * GATES + n]);
    }
}

// ---------------- bf16 U fragment pre-swizzle ----------------
__global__ void build_ufragb(const float* __restrict__ U, uint32_t* __restrict__ UFB)
{
    int idx = blockIdx.x * blockDim.x + threadIdx.x;
    if (idx < 4 * 64 * 4 * 32 * 4) {
        int q    = idx & 3;
        int lane = (idx >> 2) & 31;
        int kt2  = (idx >> 7) & 3;
        int ntg  = (idx >> 9) & 63;
        int u    = idx >> 15;
        int tig = lane & 3, gg = lane >> 2;
        int kt  = kt2 * 2 + (q >> 1);
        int reg = q & 1;
        int k_lo = kt * 16 + reg * 8 + 2 * tig;
        int n = ntg * 8 + gg;
        const float* Ub = U + (size_t)u * (EMB * GATES);
        UFB[idx] = bf2(Ub[(size_t)k_lo * GATES + n], Ub[(size_t)(k_lo + 1) * GATES + n]);
    }
}

// ---------------- fused bf16 tensor-core LSTM recurrence ----------------
// grid (64, 2), block 512. ldmatrix for h fragments; fp16 zx; fp32 h out;
// optional bf16x2 h out (hb == nullptr -> skip).
__global__ __launch_bounds__(512) void lstm_tc(
    const __half* __restrict__ zx_fw, const __half* __restrict__ zx_bw,
    const uint32_t* __restrict__ uf_fw, const uint32_t* __restrict__ uf_bw,
    float* __restrict__ out_fw, float* __restrict__ out_bw,
    uint32_t* __restrict__ hb_fw, uint32_t* __restrict__ hb_bw)
{
    const int dir = blockIdx.y;
    const __half* __restrict__ zx = dir ? zx_bw : zx_fw;
    const uint32_t* __restrict__ uf = dir ? uf_bw : uf_fw;
    float* __restrict__ out = dir ? out_bw : out_fw;
    uint32_t* __restrict__ hb = dir ? hb_bw : hb_fw;

    const int b0  = blockIdx.x * 8;
    const int tid = threadIdx.x;
    const int w   = tid >> 5;
    const int lane = tid & 31;
    const int g = lane >> 2;
    const int tig = lane & 3;
    const int col0 = 8 * w + 2 * tig;

    __shared__ __align__(16) uint32_t h2[2][16][68];

    for (int q2 = tid; q2 < 2 * 16 * 68; q2 += 512) ((uint32_t*)h2)[q2] = 0u;
    float c0 = 0.f, c1 = 0.f;

    const uint4* ufp[4];
#pragma unroll
    for (int nt = 0; nt < 4; nt++)
        ufp[nt] = (const uint4*)uf + (size_t)(w + 16 * nt) * 4 * 32 + lane;

    uint32_t h_base[2];
#pragma unroll
    for (int rb2 = 0; rb2 < 2; rb2++)
        h_base[rb2] = smem_u32(&h2[rb2][lane & 15][(lane >> 4) * 4]);

    const __half* zr0 = zx + ((size_t)(b0 + g) * SEQT) * GATES + col0;
    float* or0 = out + ((size_t)(b0 + g) * SEQT) * HID + col0;
    uint32_t* hr0 = hb ? hb + (((size_t)(b0 + g) * SEQT) * HID + col0) / 2 : (uint32_t*)0;

    __syncthreads();

    for (int s = 0; s < SEQT; s++) {
        const int t = dir ? (SEQT - 1 - s) : s;
        const int rb = s & 1;
        const int wb = rb ^ 1;

        float2 zv0[4];
#pragma unroll
        for (int nt = 0; nt < 4; nt++) {
            __half2 hz = *(const __half2*)&zr0[(size_t)t * GATES + 128 * nt];
            zv0[nt] = __half22float2(hz);
        }

        float acc[4][4];
#pragma unroll
        for (int nt = 0; nt < 4; nt++)
#pragma unroll
            for (int q = 0; q < 4; q++) acc[nt][q] = 0.f;

        uint4 bv[4];
#pragma unroll
        for (int nt = 0; nt < 4; nt++) bv[nt] = ufp[nt][0];

#pragma unroll
        for (int kt2 = 0; kt2 < 4; kt2++) {
            uint4 nb[4];
            if (kt2 < 3) {
#pragma unroll
                for (int nt = 0; nt < 4; nt++) nb[nt] = ufp[nt][(kt2 + 1) * 32];
            }
            uint32_t ae[4], ao[4];
            ldsm4(ae[0], ae[1], ae[2], ae[3], h_base[rb] + kt2 * 64);
            ldsm4(ao[0], ao[1], ao[2], ao[3], h_base[rb] + kt2 * 64 + 32);
#pragma unroll
            for (int nt = 0; nt < 4; nt++) {
                mma_bf16(acc[nt], ae, bv[nt].x, bv[nt].y);
                mma_bf16(acc[nt], ao, bv[nt].z, bv[nt].w);
            }
#pragma unroll
            for (int nt = 0; nt < 4; nt++) bv[nt] = nb[nt];
        }

        float h00, h01;
        {
            float ig = sigm(acc[0][0] + zv0[0].x), fg = sigm(acc[1][0] + zv0[1].x);
            float gg = tanh_(acc[2][0] + zv0[2].x), og = sigm(acc[3][0] + zv0[3].x);
            c0 = fg * c0 + ig * gg;  h00 = og * tanh_(c0);
        }
        {
            float ig = sigm(acc[0][1] + zv0[0].y), fg = sigm(acc[1][1] + zv0[1].y);
            float gg = tanh_(acc[2][1] + zv0[2].y), og = sigm(acc[3][1] + zv0[3].y);
            c1 = fg * c1 + ig * gg;  h01 = og * tanh_(c1);
        }

        uint32_t hp = bf2(h00, h01);
        h2[wb][g][col0 >> 1] = hp;
        if (hr0) hr0[(size_t)t * (HID/2)] = hp;
        *(float2*)&or0[(size_t)t * HID] = make_float2(h00, h01);

        __syncthreads();
    }
}

// ---------------- final combine ----------------
__global__ void combine(const float* __restrict__ a, const float* __restrict__ b,
                        const float* __restrict__ c, const float* __restrict__ d,
                        float* __restrict__ out, int n4)
{
    int i = blockIdx.x * blockDim.x + threadIdx.x;
    if (i < n4) {
        float4 va = ((const float4*)a)[i];
        float4 vb = ((const float4*)b)[i];
        float4 vc = ((const float4*)c)[i];
        float4 vd = ((const float4*)d)[i];
        float4 o;
        o.x = 0.5f * (va.x + vb.x + vc.x + vd.x);
        o.y = 0.5f * (va.y + vb.y + vc.y + vd.y);
        o.z = 0.5f * (va.z + vb.z + vc.z + vd.z);
        o.w = 0.5f * (va.w + vb.w + vc.w + vd.w);
        ((float4*)out)[i] = o;
    }
}

// ---------------- launch ----------------
extern "C" void kernel_launch(void* const* d_in, const int* in_sizes, int n_in,
                              void* d_out, int out_size)
{
    const float* x = (const float*)d_in[0];
    const float* W = (const float*)d_in[1];
    const float* U = (const float*)d_in[2];
    const float* b = (const float*)d_in[3];

    __half *zxf, *zxb;
    float *s0f, *s0b, *s1f, *s1b;
    uint32_t *xb, *hb0f, *hb0b, *Wtb, *UFB;
    cudaGetSymbolAddress((void**)&zxf, g_zx_fw);
    cudaGetSymbolAddress((void**)&zxb, g_zx_bw);
    cudaGetSymbolAddress((void**)&s0f, g_s0f);
    cudaGetSymbolAddress((void**)&s0b, g_s0b);
    cudaGetSymbolAddress((void**)&s1f, g_s1f);
    cudaGetSymbolAddress((void**)&s1b, g_s1b);
    cudaGetSymbolAddress((void**)&xb, g_xb);
    cudaGetSymbolAddress((void**)&hb0f, g_hb0f);
    cudaGetSymbolAddress((void**)&hb0b, g_hb0b);
    cudaGetSymbolAddress((void**)&Wtb, g_Wtb);
    cudaGetSymbolAddress((void**)&UFB, g_UfragB);

    cudaFuncSetAttribute(gemm_bf, cudaFuncAttributeMaxDynamicSharedMemorySize, GSMEM);

    const size_t WBSZ = (size_t)GATES * (EMB/2);   // 32768 uint32
    const size_t UFSZ = 64 * 4 * 32 * 4;           // 32768 uint32
    const float* b00 = b;           const float* b01 = b + GATES;
    const float* b10 = b + 2*GATES; const float* b11 = b + 3*GATES;
    uint32_t* Wt00 = Wtb;            uint32_t* Wt01 = Wtb + WBSZ;
    uint32_t* Wt10 = Wtb + 2*WBSZ;   uint32_t* Wt11 = Wtb + 3*WBSZ;
    uint32_t* UF00 = UFB;            uint32_t* UF01 = UFB + UFSZ;
    uint32_t* UF10 = UFB + 2*UFSZ;   uint32_t* UF11 = UFB + 3*UFSZ;

    int nx2 = MTOT * EMB / 2;
    convert_x<<<(nx2 + 255) / 256, 256>>>(x, xb, nx2);
    build_wtb<<<(4 * GATES * (EMB/2) + 255) / 256, 256>>>(W, Wtb);
    build_ufragb<<<(4 * 64 * 4 * 32 * 4 + 255) / 256, 256>>>(U, UFB);

    dim3 gg(GATES / 128, MTOT / 128, 2);   // (4, 800, 2) — fw+bw fused
    dim3 lg(BATCH / 8, 2);                 // (64, 2)

    gemm_bf<<<gg, 256, GSMEM>>>(xb, xb, Wt00, Wt01, b00, b01, zxf, zxb);
    lstm_tc<<<lg, 512>>>(zxf, zxb, UF00, UF01, s0f, s0b, hb0f, hb0b);

    gemm_bf<<<gg, 256, GSMEM>>>(hb0f, hb0b, Wt10, Wt11, b10, b11, zxf, zxb);
    lstm_tc<<<lg, 512>>>(zxf, zxb, UF10, UF11, s1f, s1b, (uint32_t*)0, (uint32_t*)0);

    int n4 = MTOT * HID / 4;
    combine<<<(n4 + 255) / 256, 256>>>(s1f, s0f, s1b, s0b, (float*)d_out, n4);
}